// round 7
// baseline (speedup 1.0000x reference)
#include <cuda_runtime.h>

// Performer FAVOR+ — fused persistent kernel, tf32 mma.sync + ldmatrix.
// R7: single-plane fp32 staging (hi/lo split in registers post-ldmatrix),
// diag folded into staging via half-warp shuffles, k-tile syncs 4->2.

#define BHn 128
#define Nn  4096
#define Dn  64
#define Mn  256
#define NTILES 64

#define NORMV 0.35355339059327378f
#define RATIO 0.0625f
#define EPSV  1e-4f

#define PJ_S 68
#define KQ_S 68
#define VT_S 68
#define ET_S 68
#define QP_S 268
#define CT_S 268

__device__ __forceinline__ void mma8(float d[4], const unsigned a[4],
                                     const unsigned b[2]) {
  asm volatile(
      "mma.sync.aligned.m16n8k8.row.col.f32.tf32.tf32.f32 "
      "{%0,%1,%2,%3},{%4,%5,%6,%7},{%8,%9},{%0,%1,%2,%3};"
      : "+f"(d[0]), "+f"(d[1]), "+f"(d[2]), "+f"(d[3])
      : "r"(a[0]), "r"(a[1]), "r"(a[2]), "r"(a[3]), "r"(b[0]), "r"(b[1]));
}
__device__ __forceinline__ void ldsm4(unsigned r[4], unsigned addr) {
  asm volatile(
      "ldmatrix.sync.aligned.m8n8.x4.shared.b16 {%0,%1,%2,%3}, [%4];"
      : "=r"(r[0]), "=r"(r[1]), "=r"(r[2]), "=r"(r[3]) : "r"(addr));
}
__device__ __forceinline__ unsigned rna(float x) {
  unsigned r; asm("cvt.rna.tf32.f32 %0, %1;" : "=r"(r) : "f"(x)); return r;
}
__device__ __forceinline__ float rnaf(float x) { return __uint_as_float(rna(x)); }
__device__ __forceinline__ unsigned s2u(const void* p) {
  return (unsigned)__cvta_generic_to_shared(p);
}
__device__ __forceinline__ int a_off(int lane, int S) {
  return (((lane >> 3) & 1) * 8 + (lane & 7)) * S + (lane >> 4) * 4;
}
__device__ __forceinline__ int b_off(int lane, int S) {
  return ((lane >> 4) * 8 + (lane & 7)) * S + ((lane >> 3) & 1) * 4;
}
// split a raw-f32 ldmatrix fragment into tf32 hi/lo planes (registers only)
__device__ __forceinline__ void split4(const unsigned af[4], unsigned ah[4],
                                       unsigned al[4]) {
#pragma unroll
  for (int j = 0; j < 4; j++) {
    float x = __uint_as_float(af[j]);
    ah[j] = rna(x);
    al[j] = rna(x - __uint_as_float(ah[j]));
  }
}

// ---------------------------------------------------------------------------
__global__ __launch_bounds__(512, 1) void fused_kernel(
    const float* __restrict__ qg, const float* __restrict__ kg,
    const float* __restrict__ vg, const float* __restrict__ projg,
    float* __restrict__ outg) {
  extern __shared__ float sm[];
  float* bufP   = sm;                 // 17408: proj -> E_T (68) -> qp (268)
  float* bufC   = bufP + 17408;       // 17152: ctx [64][268]
  float* vT_s   = bufC + 17152;       // 4352
  float* kq_s   = vT_s + 4352;        // 4352: full-f32 staged k/q (scaled)
  float* diag_s = kq_s + 4352;        // 64
  float* vsum_s = diag_s + 64;        // 64
  float* red_s  = vsum_s + 64;        // 32
  float* ksum_s = red_s + 32;         // 256
  float* sub_s  = ksum_s + 256;       // 64
  float* rmx    = sub_s + 64;         // 1024 [64][16]
  float* den    = rmx + 1024;         // 1024 [64][16]
  float* denom_s = den + 1024;        // 64

  const int bh = blockIdx.x, tid = threadIdx.x;
  const int lane = tid & 31, wid = tid >> 5;
  const int gid = lane >> 2, tig = lane & 3;
  const int m0 = wid * 16;

  const unsigned u_P = s2u(bufP), u_C = s2u(bufC), u_vT = s2u(vT_s);
  const unsigned u_kq = s2u(kq_s);
  const int aoKQ = a_off(lane, KQ_S), boPJ = b_off(lane, PJ_S);
  const int aoET = a_off(lane, ET_S), boVT = b_off(lane, VT_S);
  const int aoQP = a_off(lane, QP_S), boCT = b_off(lane, CT_S);

  const float4* kb4 = (const float4*)(kg + (size_t)bh * Nn * Dn);
  const float4* vb4 = (const float4*)(vg + (size_t)bh * Nn * Dn);
  const float4* qb4 = (const float4*)(qg + (size_t)bh * Nn * Dn);

  // ---- proj -> smem (rna), extract B fragments into registers ----
  for (int i = tid; i < 4096; i += 512) {
    float4 p = ((const float4*)projg)[i];
    p.x = rnaf(p.x); p.y = rnaf(p.y); p.z = rnaf(p.z); p.w = rnaf(p.w);
    *(float4*)&bufP[(i >> 4) * PJ_S + (i & 15) * 4] = p;
  }
  __syncthreads();
  unsigned projB[8][4];
#pragma unroll
  for (int ks = 0; ks < 8; ks++)
    ldsm4(projB[ks], u_P + (unsigned)(m0 * PJ_S + ks * 8 + boPJ) * 4u);
  __syncthreads();  // bufP free

  // =======================================================================
  // K/V pass
  // =======================================================================
  float C2[8][4];
#pragma unroll
  for (int e = 0; e < 8; e++)
#pragma unroll
    for (int j = 0; j < 4; j++) C2[e][j] = 0.f;
  float uacc[2][2] = {};
  float vsum = 0.f, dmax = -1e30f;

  float4 kpre[2], vpre[2];
  kpre[0] = kb4[tid]; kpre[1] = kb4[512 + tid];
  vpre[0] = vb4[tid]; vpre[1] = vb4[512 + tid];

  for (int t = 0; t < NTILES; t++) {
    __syncthreads();  // kq/vT/E_T free
#pragma unroll
    for (int u = 0; u < 2; u++) {
      int i = u * 512 + tid;
      int r = i >> 4, c4 = (i & 15) * 4;
      float4 kv = kpre[u];
      kv.x *= NORMV; kv.y *= NORMV; kv.z *= NORMV; kv.w *= NORMV;
      *(float4*)&kq_s[r * KQ_S + c4] = kv;
      // diag: 16 staging threads of this row reduce their sumsq
      float s = kv.x * kv.x + kv.y * kv.y + kv.z * kv.z + kv.w * kv.w;
      s += __shfl_xor_sync(0xffffffffu, s, 1);
      s += __shfl_xor_sync(0xffffffffu, s, 2);
      s += __shfl_xor_sync(0xffffffffu, s, 4);
      s += __shfl_xor_sync(0xffffffffu, s, 8);
      if ((tid & 15) == 0) diag_s[r] = 0.5f * s;
      float4 vv = vpre[u];
      vT_s[(c4 + 0) * VT_S + r] = rnaf(vv.x);
      vT_s[(c4 + 1) * VT_S + r] = rnaf(vv.y);
      vT_s[(c4 + 2) * VT_S + r] = rnaf(vv.z);
      vT_s[(c4 + 3) * VT_S + r] = rnaf(vv.w);
    }
    if (t < NTILES - 1) {
      kpre[0] = kb4[(t + 1) * 1024 + tid];
      kpre[1] = kb4[(t + 1) * 1024 + 512 + tid];
      vpre[0] = vb4[(t + 1) * 1024 + tid];
      vpre[1] = vb4[(t + 1) * 1024 + 512 + tid];
    }
    __syncthreads();  // staged data + diag ready

    if (tid < 64) {  // vsum partial (overlaps other warps' dash)
      float vs = 0.f;
#pragma unroll 8
      for (int r = 0; r < 64; r++) vs += vT_s[tid * VT_S + r];
      vsum += vs;
    }

    // dash = k @ proj^T (2-pass compensated tf32; A split in registers)
    float dfrag[4][2][4];
#pragma unroll
    for (int g = 0; g < 4; g++)
#pragma unroll
      for (int mt = 0; mt < 2; mt++)
#pragma unroll
        for (int j = 0; j < 4; j++) dfrag[g][mt][j] = 0.f;

#pragma unroll
    for (int ks = 0; ks < 8; ks++) {
#pragma unroll
      for (int g = 0; g < 4; g++) {
        unsigned af[4], ah[4], al[4];
        ldsm4(af, u_kq + (unsigned)(g * 16 * KQ_S + ks * 8 + aoKQ) * 4u);
        split4(af, ah, al);
        mma8(dfrag[g][0], ah, projB[ks]);
        mma8(dfrag[g][0], al, projB[ks]);
        mma8(dfrag[g][1], ah, projB[ks] + 2);
        mma8(dfrag[g][1], al, projB[ks] + 2);
      }
    }

    // exp -> E_T (bufP); U and max  (no sync needed: diag staged, buffers ok)
#pragma unroll
    for (int g = 0; g < 4; g++) {
      int r = g * 16 + gid;
      float dg0 = diag_s[r], dg1 = diag_s[r + 8];
#pragma unroll
      for (int mt = 0; mt < 2; mt++) {
        int m = m0 + mt * 8 + 2 * tig;
        float d0 = dfrag[g][mt][0], d1 = dfrag[g][mt][1];
        float d2 = dfrag[g][mt][2], d3 = dfrag[g][mt][3];
        dmax = fmaxf(dmax, fmaxf(fmaxf(d0, d1), fmaxf(d2, d3)));
        float e0 = __expf(d0 - dg0), e1 = __expf(d1 - dg0);
        float e2 = __expf(d2 - dg1), e3 = __expf(d3 - dg1);
        uacc[mt][0] += e0 + e2;
        uacc[mt][1] += e1 + e3;
        bufP[m * ET_S + r]           = rnaf(e0);
        bufP[(m + 1) * ET_S + r]     = rnaf(e1);
        bufP[m * ET_S + r + 8]       = rnaf(e2);
        bufP[(m + 1) * ET_S + r + 8] = rnaf(e3);
      }
    }
    __syncthreads();  // E ready

    // C2 += E^T(m-slice) @ V
#pragma unroll
    for (int ks = 0; ks < 8; ks++) {
      unsigned a[4];
      ldsm4(a, u_P + (unsigned)(m0 * ET_S + ks * 8 + aoET) * 4u);
#pragma unroll
      for (int ep = 0; ep < 4; ep++) {
        unsigned b[4];
        ldsm4(b, u_vT + (unsigned)(ep * 16 * VT_S + ks * 8 + boVT) * 4u);
        mma8(C2[ep * 2], a, b);
        mma8(C2[ep * 2 + 1], a, b + 2);
      }
    }
  }

  // ---- finalize ksum + ctx (all in smem) ----
  float wm = dmax;
#pragma unroll
  for (int off = 16; off; off >>= 1)
    wm = fmaxf(wm, __shfl_xor_sync(0xffffffffu, wm, off));
  if (lane == 0) red_s[wid] = wm;
  if (tid < 64) vsum_s[tid] = vsum;
  __syncthreads();
  if (tid == 0) {
    float mm = red_s[0];
#pragma unroll
    for (int w = 1; w < 16; w++) mm = fmaxf(mm, red_s[w]);
    red_s[16] = mm;
  }
  __syncthreads();
  const float scale = __expf(-red_s[16]);

#pragma unroll
  for (int mt = 0; mt < 2; mt++) {
#pragma unroll
    for (int j = 0; j < 2; j++) {
      float u = uacc[mt][j];
      u += __shfl_xor_sync(0xffffffffu, u, 4);
      u += __shfl_xor_sync(0xffffffffu, u, 8);
      u += __shfl_xor_sync(0xffffffffu, u, 16);
      if (gid == 0)
        ksum_s[m0 + mt * 8 + 2 * tig + j] =
            RATIO * (scale * u + EPSV * (float)Nn);
    }
  }

  {
    int m = m0 + gid;
#pragma unroll
    for (int et = 0; et < 8; et++) {
      int e = et * 8 + 2 * tig;
      bufC[e * CT_S + m]           = rnaf(RATIO * (scale * C2[et][0] + EPSV * vsum_s[e]));
      bufC[(e + 1) * CT_S + m]     = rnaf(RATIO * (scale * C2[et][1] + EPSV * vsum_s[e + 1]));
      bufC[e * CT_S + m + 8]       = rnaf(RATIO * (scale * C2[et][2] + EPSV * vsum_s[e]));
      bufC[(e + 1) * CT_S + m + 8] = rnaf(RATIO * (scale * C2[et][3] + EPSV * vsum_s[e + 1]));
    }
  }
  __syncthreads();  // ctx + ksum ready

  // =======================================================================
  // Q pass: 64 tiles against smem-resident ctx
  // =======================================================================
  float ksv[2][2];
#pragma unroll
  for (int mt = 0; mt < 2; mt++) {
    ksv[mt][0] = ksum_s[m0 + mt * 8 + 2 * tig];
    ksv[mt][1] = ksum_s[m0 + mt * 8 + 2 * tig + 1];
  }
  const int rg = (wid & 3) * 16;
  const int eh = (wid >> 2) * 16;

  float4 qpre[2];
  qpre[0] = qb4[tid]; qpre[1] = qb4[512 + tid];

  for (int t = 0; t < NTILES; t++) {
    __syncthreads();  // kq + bufP(qp) free
#pragma unroll
    for (int u = 0; u < 2; u++) {
      int i = u * 512 + tid;
      int r = i >> 4, c4 = (i & 15) * 4;
      float4 qv = qpre[u];
      qv.x *= NORMV; qv.y *= NORMV; qv.z *= NORMV; qv.w *= NORMV;
      *(float4*)&kq_s[r * KQ_S + c4] = qv;
      float s = qv.x * qv.x + qv.y * qv.y + qv.z * qv.z + qv.w * qv.w;
      s += __shfl_xor_sync(0xffffffffu, s, 1);
      s += __shfl_xor_sync(0xffffffffu, s, 2);
      s += __shfl_xor_sync(0xffffffffu, s, 4);
      s += __shfl_xor_sync(0xffffffffu, s, 8);
      if ((tid & 15) == 0) diag_s[r] = 0.5f * s;
    }
    if (t < NTILES - 1) {
      qpre[0] = qb4[(t + 1) * 1024 + tid];
      qpre[1] = qb4[(t + 1) * 1024 + 512 + tid];
    }
    __syncthreads();

    // dash (A split in registers, B from projB)
    float dfrag[4][2][4];
#pragma unroll
    for (int g = 0; g < 4; g++)
#pragma unroll
      for (int mt = 0; mt < 2; mt++)
#pragma unroll
        for (int j = 0; j < 4; j++) dfrag[g][mt][j] = 0.f;

#pragma unroll
    for (int ks = 0; ks < 8; ks++) {
#pragma unroll
      for (int g = 0; g < 4; g++) {
        unsigned af[4], ah[4], al[4];
        ldsm4(af, u_kq + (unsigned)(g * 16 * KQ_S + ks * 8 + aoKQ) * 4u);
        split4(af, ah, al);
        mma8(dfrag[g][0], ah, projB[ks]);
        mma8(dfrag[g][0], al, projB[ks]);
        mma8(dfrag[g][1], ah, projB[ks] + 2);
        mma8(dfrag[g][1], al, projB[ks] + 2);
      }
    }

    // per-warp row-max partials
#pragma unroll
    for (int g = 0; g < 4; g++) {
      float mlo = -1e30f, mhi = -1e30f;
#pragma unroll
      for (int mt = 0; mt < 2; mt++) {
        mlo = fmaxf(mlo, fmaxf(dfrag[g][mt][0], dfrag[g][mt][1]));
        mhi = fmaxf(mhi, fmaxf(dfrag[g][mt][2], dfrag[g][mt][3]));
      }
      mlo = fmaxf(mlo, __shfl_xor_sync(0xffffffffu, mlo, 1));
      mlo = fmaxf(mlo, __shfl_xor_sync(0xffffffffu, mlo, 2));
      mhi = fmaxf(mhi, __shfl_xor_sync(0xffffffffu, mhi, 1));
      mhi = fmaxf(mhi, __shfl_xor_sync(0xffffffffu, mhi, 2));
      if (tig == 0) {
        rmx[(g * 16 + gid) * 16 + wid] = mlo;
        rmx[(g * 16 + gid + 8) * 16 + wid] = mhi;
      }
    }
    __syncthreads();  // rmx ready

    if (tid < 64) {
      float r0 = rmx[tid * 16];
#pragma unroll
      for (int w = 1; w < 16; w++) r0 = fmaxf(r0, rmx[tid * 16 + w]);
      sub_s[tid] = diag_s[tid] + r0;
    }
    __syncthreads();  // sub ready

    // q' = ratio*(exp(dash - sub) + eps) -> bufP; denom partials folded in
#pragma unroll
    for (int g = 0; g < 4; g++) {
      int r = g * 16 + gid;
      float sub0 = sub_s[r], sub1 = sub_s[r + 8];
      float ds0 = 0.f, ds1 = 0.f;
#pragma unroll
      for (int mt = 0; mt < 2; mt++) {
        int m = m0 + mt * 8 + 2 * tig;
        float q0 = RATIO * (__expf(dfrag[g][mt][0] - sub0) + EPSV);
        float q1 = RATIO * (__expf(dfrag[g][mt][1] - sub0) + EPSV);
        float q2 = RATIO * (__expf(dfrag[g][mt][2] - sub1) + EPSV);
        float q3 = RATIO * (__expf(dfrag[g][mt][3] - sub1) + EPSV);
        ds0 += q0 * ksv[mt][0] + q1 * ksv[mt][1];
        ds1 += q2 * ksv[mt][0] + q3 * ksv[mt][1];
        *(float2*)&bufP[r * QP_S + m] = make_float2(rnaf(q0), rnaf(q1));
        *(float2*)&bufP[(r + 8) * QP_S + m] = make_float2(rnaf(q2), rnaf(q3));
      }
      ds0 += __shfl_xor_sync(0xffffffffu, ds0, 1);
      ds0 += __shfl_xor_sync(0xffffffffu, ds0, 2);
      ds1 += __shfl_xor_sync(0xffffffffu, ds1, 1);
      ds1 += __shfl_xor_sync(0xffffffffu, ds1, 2);
      if (tig == 0) {
        den[r * 16 + wid] = ds0;
        den[(r + 8) * 16 + wid] = ds1;
      }
    }
    __syncthreads();  // qp + den ready

    if (tid < 64) {
      float s = 0.f;
#pragma unroll
      for (int w = 0; w < 16; w++) s += den[tid * 16 + w];
      denom_s[tid] = s;
    }

    // out = q' @ ctx
    float ofrag[2][4];
#pragma unroll
    for (int et = 0; et < 2; et++)
#pragma unroll
      for (int j = 0; j < 4; j++) ofrag[et][j] = 0.f;

#pragma unroll 8
    for (int ks = 0; ks < 32; ks++) {
      unsigned a[4], b[4];
      ldsm4(a, u_P + (unsigned)(rg * QP_S + ks * 8 + aoQP) * 4u);
      ldsm4(b, u_C + (unsigned)(eh * CT_S + ks * 8 + boCT) * 4u);
      mma8(ofrag[0], a, b);
      mma8(ofrag[1], a, b + 2);
    }
    __syncthreads();  // denom ready

    float inv0 = 1.f / denom_s[rg + gid];
    float inv1 = 1.f / denom_s[rg + gid + 8];
    float* ob = outg + ((size_t)bh * Nn + (size_t)t * 64) * Dn;
#pragma unroll
    for (int et = 0; et < 2; et++) {
      int e = eh + et * 8 + 2 * tig;
      int r = rg + gid;
      *(float2*)&ob[r * Dn + e] =
          make_float2(ofrag[et][0] * inv0, ofrag[et][1] * inv0);
      *(float2*)&ob[(r + 8) * Dn + e] =
          make_float2(ofrag[et][2] * inv1, ofrag[et][3] * inv1);
    }
  }
}

// ---------------------------------------------------------------------------
extern "C" void kernel_launch(void* const* d_in, const int* in_sizes, int n_in,
                              void* d_out, int out_size) {
  const float* q    = (const float*)d_in[0];
  const float* k    = (const float*)d_in[1];
  const float* v    = (const float*)d_in[2];
  const float* proj = (const float*)d_in[3];
  float* out = (float*)d_out;

  const int smem =
      (17408 + 17152 + 4352 + 4352 + 64 + 64 + 32 + 256 + 64 + 1024 + 1024 +
       64) * 4;

  cudaFuncSetAttribute(fused_kernel, cudaFuncAttributeMaxDynamicSharedMemorySize, smem);
  fused_kernel<<<BHn, 512, smem>>>(q, k, v, proj, out);
}

// round 9
// speedup vs baseline: 1.7109x; 1.7109x over previous
#include <cuda_runtime.h>

// Performer FAVOR+ — fused persistent kernel, tf32 mma.sync + ldmatrix.
// R8: R6 two-plane staging + vT double-buffer (k-tile 2 syncs), q-tile
// 3 syncs (rmax/denom read per-thread), vsum folded into staging regs.

#define BHn 128
#define Nn  4096
#define Dn  64
#define Mn  256
#define NTILES 64

#define NORMV 0.35355339059327378f
#define RATIO 0.0625f
#define EPSV  1e-4f

#define PJ_S 68
#define KQ_S 68
#define VT_S 68
#define ET_S 68
#define QP_S 268
#define CT_S 268

__device__ __forceinline__ void mma8(float d[4], const unsigned a[4],
                                     const unsigned b[2]) {
  asm volatile(
      "mma.sync.aligned.m16n8k8.row.col.f32.tf32.tf32.f32 "
      "{%0,%1,%2,%3},{%4,%5,%6,%7},{%8,%9},{%0,%1,%2,%3};"
      : "+f"(d[0]), "+f"(d[1]), "+f"(d[2]), "+f"(d[3])
      : "r"(a[0]), "r"(a[1]), "r"(a[2]), "r"(a[3]), "r"(b[0]), "r"(b[1]));
}
__device__ __forceinline__ void ldsm4(unsigned r[4], unsigned addr) {
  asm volatile(
      "ldmatrix.sync.aligned.m8n8.x4.shared.b16 {%0,%1,%2,%3}, [%4];"
      : "=r"(r[0]), "=r"(r[1]), "=r"(r[2]), "=r"(r[3]) : "r"(addr));
}
__device__ __forceinline__ unsigned rna(float x) {
  unsigned r; asm("cvt.rna.tf32.f32 %0, %1;" : "=r"(r) : "f"(x)); return r;
}
__device__ __forceinline__ float rnaf(float x) { return __uint_as_float(rna(x)); }
__device__ __forceinline__ unsigned s2u(const void* p) {
  return (unsigned)__cvta_generic_to_shared(p);
}
__device__ __forceinline__ int a_off(int lane, int S) {
  return (((lane >> 3) & 1) * 8 + (lane & 7)) * S + (lane >> 4) * 4;
}
__device__ __forceinline__ int b_off(int lane, int S) {
  return ((lane >> 4) * 8 + (lane & 7)) * S + ((lane >> 3) & 1) * 4;
}

// ---------------------------------------------------------------------------
__global__ __launch_bounds__(512, 1) void fused_kernel(
    const float* __restrict__ qg, const float* __restrict__ kg,
    const float* __restrict__ vg, const float* __restrict__ projg,
    float* __restrict__ outg) {
  extern __shared__ float sm[];
  float* bufP   = sm;                 // 17408: proj -> E_T (68) -> qp (268)
  float* bufC   = bufP + 17408;       // 17152: ctx [64][268]
  float* vT0    = bufC + 17152;       // 4352 (double buffer 0)
  float* vT1    = vT0 + 4352;         // 4352 (double buffer 1)
  float* kq_hi  = vT1 + 4352;         // 4352
  float* kq_lo  = kq_hi + 4352;       // 4352
  float* diag_s = kq_lo + 4352;       // 64
  float* vsum_s = diag_s + 64;        // 64
  float* red_s  = vsum_s + 64;        // 32
  float* ksum_s = red_s + 32;         // 256
  float* rmx    = ksum_s + 256;       // 1024 [64][16] (also vsum scratch)
  float* den    = rmx + 1024;         // 1024 [64][16]

  const int bh = blockIdx.x, tid = threadIdx.x;
  const int lane = tid & 31, wid = tid >> 5;
  const int gid = lane >> 2, tig = lane & 3;
  const int m0 = wid * 16;

  const unsigned u_P = s2u(bufP), u_C = s2u(bufC);
  const unsigned u_vT0 = s2u(vT0), u_vT1 = s2u(vT1);
  const unsigned u_khi = s2u(kq_hi), u_klo = s2u(kq_lo);
  const int aoKQ = a_off(lane, KQ_S), boPJ = b_off(lane, PJ_S);
  const int aoET = a_off(lane, ET_S), boVT = b_off(lane, VT_S);
  const int aoQP = a_off(lane, QP_S), boCT = b_off(lane, CT_S);

  const float4* kb4 = (const float4*)(kg + (size_t)bh * Nn * Dn);
  const float4* vb4 = (const float4*)(vg + (size_t)bh * Nn * Dn);
  const float4* qb4 = (const float4*)(qg + (size_t)bh * Nn * Dn);

  // ---- proj -> smem (rna), extract B fragments into registers ----
  for (int i = tid; i < 4096; i += 512) {
    float4 p = ((const float4*)projg)[i];
    p.x = rnaf(p.x); p.y = rnaf(p.y); p.z = rnaf(p.z); p.w = rnaf(p.w);
    *(float4*)&bufP[(i >> 4) * PJ_S + (i & 15) * 4] = p;
  }
  __syncthreads();
  unsigned projB[8][4];
#pragma unroll
  for (int ks = 0; ks < 8; ks++)
    ldsm4(projB[ks], u_P + (unsigned)(m0 * PJ_S + ks * 8 + boPJ) * 4u);
  __syncthreads();  // bufP free

  // =======================================================================
  // K/V pass (2 syncs per tile)
  // =======================================================================
  float C2[8][4];
#pragma unroll
  for (int e = 0; e < 8; e++)
#pragma unroll
    for (int j = 0; j < 4; j++) C2[e][j] = 0.f;
  float uacc[2][2] = {};
  float4 vsum4 = make_float4(0.f, 0.f, 0.f, 0.f);
  float dmax = -1e30f;

  float4 kpre[2], vpre[2];
  kpre[0] = kb4[tid]; kpre[1] = kb4[512 + tid];
  vpre[0] = vb4[tid]; vpre[1] = vb4[512 + tid];

  for (int t = 0; t < NTILES; t++) {
    float* vT_s = (t & 1) ? vT1 : vT0;
    const unsigned u_vT = (t & 1) ? u_vT1 : u_vT0;
    // stage (no top sync: writes only kq/vT[buf]/diag, none read by prev C-mma)
#pragma unroll
    for (int u = 0; u < 2; u++) {
      int i = u * 512 + tid;
      int r = i >> 4, c4 = (i & 15) * 4;
      float4 kv = kpre[u];
      kv.x *= NORMV; kv.y *= NORMV; kv.z *= NORMV; kv.w *= NORMV;
      float4 hi, lo;
      hi.x = rnaf(kv.x); lo.x = kv.x - hi.x;
      hi.y = rnaf(kv.y); lo.y = kv.y - hi.y;
      hi.z = rnaf(kv.z); lo.z = kv.z - hi.z;
      hi.w = rnaf(kv.w); lo.w = kv.w - hi.w;
      *(float4*)&kq_hi[r * KQ_S + c4] = hi;
      *(float4*)&kq_lo[r * KQ_S + c4] = lo;
      float s = kv.x * kv.x + kv.y * kv.y + kv.z * kv.z + kv.w * kv.w;
      s += __shfl_xor_sync(0xffffffffu, s, 1);
      s += __shfl_xor_sync(0xffffffffu, s, 2);
      s += __shfl_xor_sync(0xffffffffu, s, 4);
      s += __shfl_xor_sync(0xffffffffu, s, 8);
      if ((tid & 15) == 0) diag_s[r] = 0.5f * s;
      float4 vv = vpre[u];
      vsum4.x += vv.x; vsum4.y += vv.y; vsum4.z += vv.z; vsum4.w += vv.w;
      vT_s[(c4 + 0) * VT_S + r] = rnaf(vv.x);
      vT_s[(c4 + 1) * VT_S + r] = rnaf(vv.y);
      vT_s[(c4 + 2) * VT_S + r] = rnaf(vv.z);
      vT_s[(c4 + 3) * VT_S + r] = rnaf(vv.w);
    }
    if (t < NTILES - 1) {
      kpre[0] = kb4[(t + 1) * 1024 + tid];
      kpre[1] = kb4[(t + 1) * 1024 + 512 + tid];
      vpre[0] = vb4[(t + 1) * 1024 + tid];
      vpre[1] = vb4[(t + 1) * 1024 + 512 + tid];
    }
    __syncthreads();  // staged + diag ready; prev C-mma done (bufP writable)

    // dash = k @ proj^T (2-pass compensated tf32, planes pre-split in smem)
    float dfrag[4][2][4];
#pragma unroll
    for (int g = 0; g < 4; g++)
#pragma unroll
      for (int mt = 0; mt < 2; mt++)
#pragma unroll
        for (int j = 0; j < 4; j++) dfrag[g][mt][j] = 0.f;

#pragma unroll
    for (int ks = 0; ks < 8; ks++) {
#pragma unroll
      for (int g = 0; g < 4; g++) {
        unsigned ah[4], al[4];
        ldsm4(ah, u_khi + (unsigned)(g * 16 * KQ_S + ks * 8 + aoKQ) * 4u);
        ldsm4(al, u_klo + (unsigned)(g * 16 * KQ_S + ks * 8 + aoKQ) * 4u);
        mma8(dfrag[g][0], ah, projB[ks]);
        mma8(dfrag[g][0], al, projB[ks]);
        mma8(dfrag[g][1], ah, projB[ks] + 2);
        mma8(dfrag[g][1], al, projB[ks] + 2);
      }
    }

    // exp -> E_T (bufP); U and max
#pragma unroll
    for (int g = 0; g < 4; g++) {
      int r = g * 16 + gid;
      float dg0 = diag_s[r], dg1 = diag_s[r + 8];
#pragma unroll
      for (int mt = 0; mt < 2; mt++) {
        int m = m0 + mt * 8 + 2 * tig;
        float d0 = dfrag[g][mt][0], d1 = dfrag[g][mt][1];
        float d2 = dfrag[g][mt][2], d3 = dfrag[g][mt][3];
        dmax = fmaxf(dmax, fmaxf(fmaxf(d0, d1), fmaxf(d2, d3)));
        float e0 = __expf(d0 - dg0), e1 = __expf(d1 - dg0);
        float e2 = __expf(d2 - dg1), e3 = __expf(d3 - dg1);
        uacc[mt][0] += e0 + e2;
        uacc[mt][1] += e1 + e3;
        bufP[m * ET_S + r]           = rnaf(e0);
        bufP[(m + 1) * ET_S + r]     = rnaf(e1);
        bufP[m * ET_S + r + 8]       = rnaf(e2);
        bufP[(m + 1) * ET_S + r + 8] = rnaf(e3);
      }
    }
    __syncthreads();  // E ready

    // C2 += E^T(m-slice) @ V
#pragma unroll
    for (int ks = 0; ks < 8; ks++) {
      unsigned a[4];
      ldsm4(a, u_P + (unsigned)(m0 * ET_S + ks * 8 + aoET) * 4u);
#pragma unroll
      for (int ep = 0; ep < 4; ep++) {
        unsigned b[4];
        ldsm4(b, u_vT + (unsigned)(ep * 16 * VT_S + ks * 8 + boVT) * 4u);
        mma8(C2[ep * 2], a, b);
        mma8(C2[ep * 2 + 1], a, b + 2);
      }
    }
  }

  // ---- finalize ksum + ctx (all in smem) ----
  float wm = dmax;
#pragma unroll
  for (int off = 16; off; off >>= 1)
    wm = fmaxf(wm, __shfl_xor_sync(0xffffffffu, wm, off));
  if (lane == 0) red_s[wid] = wm;
  // vsum: lanes l and l^16 share column set (tid&15)
  vsum4.x += __shfl_xor_sync(0xffffffffu, vsum4.x, 16);
  vsum4.y += __shfl_xor_sync(0xffffffffu, vsum4.y, 16);
  vsum4.z += __shfl_xor_sync(0xffffffffu, vsum4.z, 16);
  vsum4.w += __shfl_xor_sync(0xffffffffu, vsum4.w, 16);
  if (lane < 16) *(float4*)&rmx[wid * 64 + lane * 4] = vsum4;
  __syncthreads();
  if (tid == 0) {
    float mm = red_s[0];
#pragma unroll
    for (int w = 1; w < 16; w++) mm = fmaxf(mm, red_s[w]);
    red_s[16] = mm;
  }
  if (tid < 64) {
    float s = 0.f;
#pragma unroll
    for (int w = 0; w < 16; w++) s += rmx[w * 64 + tid];
    vsum_s[tid] = s;
  }
  __syncthreads();
  const float scale = __expf(-red_s[16]);

#pragma unroll
  for (int mt = 0; mt < 2; mt++) {
#pragma unroll
    for (int j = 0; j < 2; j++) {
      float u = uacc[mt][j];
      u += __shfl_xor_sync(0xffffffffu, u, 4);
      u += __shfl_xor_sync(0xffffffffu, u, 8);
      u += __shfl_xor_sync(0xffffffffu, u, 16);
      if (gid == 0)
        ksum_s[m0 + mt * 8 + 2 * tig + j] =
            RATIO * (scale * u + EPSV * (float)Nn);
    }
  }

  {
    int m = m0 + gid;
#pragma unroll
    for (int et = 0; et < 8; et++) {
      int e = et * 8 + 2 * tig;
      bufC[e * CT_S + m]           = rnaf(RATIO * (scale * C2[et][0] + EPSV * vsum_s[e]));
      bufC[(e + 1) * CT_S + m]     = rnaf(RATIO * (scale * C2[et][1] + EPSV * vsum_s[e + 1]));
      bufC[e * CT_S + m + 8]       = rnaf(RATIO * (scale * C2[et][2] + EPSV * vsum_s[e]));
      bufC[(e + 1) * CT_S + m + 8] = rnaf(RATIO * (scale * C2[et][3] + EPSV * vsum_s[e + 1]));
    }
  }
  __syncthreads();  // ctx + ksum ready

  // =======================================================================
  // Q pass: 64 tiles, 3 syncs per tile
  // =======================================================================
  float ksv[2][2];
#pragma unroll
  for (int mt = 0; mt < 2; mt++) {
    ksv[mt][0] = ksum_s[m0 + mt * 8 + 2 * tig];
    ksv[mt][1] = ksum_s[m0 + mt * 8 + 2 * tig + 1];
  }
  const int rg = (wid & 3) * 16;
  const int eh = (wid >> 2) * 16;

  float4 qpre[2];
  qpre[0] = qb4[tid]; qpre[1] = qb4[512 + tid];

  for (int t = 0; t < NTILES; t++) {
    // stage (no top sync: writes only kq/diag)
#pragma unroll
    for (int u = 0; u < 2; u++) {
      int i = u * 512 + tid;
      int r = i >> 4, c4 = (i & 15) * 4;
      float4 qv = qpre[u];
      qv.x *= NORMV; qv.y *= NORMV; qv.z *= NORMV; qv.w *= NORMV;
      float4 hi, lo;
      hi.x = rnaf(qv.x); lo.x = qv.x - hi.x;
      hi.y = rnaf(qv.y); lo.y = qv.y - hi.y;
      hi.z = rnaf(qv.z); lo.z = qv.z - hi.z;
      hi.w = rnaf(qv.w); lo.w = qv.w - hi.w;
      *(float4*)&kq_hi[r * KQ_S + c4] = hi;
      *(float4*)&kq_lo[r * KQ_S + c4] = lo;
      float s = qv.x * qv.x + qv.y * qv.y + qv.z * qv.z + qv.w * qv.w;
      s += __shfl_xor_sync(0xffffffffu, s, 1);
      s += __shfl_xor_sync(0xffffffffu, s, 2);
      s += __shfl_xor_sync(0xffffffffu, s, 4);
      s += __shfl_xor_sync(0xffffffffu, s, 8);
      if ((tid & 15) == 0) diag_s[r] = 0.5f * s;
    }
    if (t < NTILES - 1) {
      qpre[0] = qb4[(t + 1) * 1024 + tid];
      qpre[1] = qb4[(t + 1) * 1024 + 512 + tid];
    }
    __syncthreads();  // staged + diag ready; prev out-mma done

    // dash
    float dfrag[4][2][4];
#pragma unroll
    for (int g = 0; g < 4; g++)
#pragma unroll
      for (int mt = 0; mt < 2; mt++)
#pragma unroll
        for (int j = 0; j < 4; j++) dfrag[g][mt][j] = 0.f;

#pragma unroll
    for (int ks = 0; ks < 8; ks++) {
#pragma unroll
      for (int g = 0; g < 4; g++) {
        unsigned ah[4], al[4];
        ldsm4(ah, u_khi + (unsigned)(g * 16 * KQ_S + ks * 8 + aoKQ) * 4u);
        ldsm4(al, u_klo + (unsigned)(g * 16 * KQ_S + ks * 8 + aoKQ) * 4u);
        mma8(dfrag[g][0], ah, projB[ks]);
        mma8(dfrag[g][0], al, projB[ks]);
        mma8(dfrag[g][1], ah, projB[ks] + 2);
        mma8(dfrag[g][1], al, projB[ks] + 2);
      }
    }

    // per-warp row-max partials
#pragma unroll
    for (int g = 0; g < 4; g++) {
      float mlo = -1e30f, mhi = -1e30f;
#pragma unroll
      for (int mt = 0; mt < 2; mt++) {
        mlo = fmaxf(mlo, fmaxf(dfrag[g][mt][0], dfrag[g][mt][1]));
        mhi = fmaxf(mhi, fmaxf(dfrag[g][mt][2], dfrag[g][mt][3]));
      }
      mlo = fmaxf(mlo, __shfl_xor_sync(0xffffffffu, mlo, 1));
      mlo = fmaxf(mlo, __shfl_xor_sync(0xffffffffu, mlo, 2));
      mhi = fmaxf(mhi, __shfl_xor_sync(0xffffffffu, mhi, 1));
      mhi = fmaxf(mhi, __shfl_xor_sync(0xffffffffu, mhi, 2));
      if (tig == 0) {
        rmx[(g * 16 + gid) * 16 + wid] = mlo;
        rmx[(g * 16 + gid + 8) * 16 + wid] = mhi;
      }
    }
    __syncthreads();  // rmx ready

    // q' = ratio*(exp(dash - diag - rowmax) + eps); rowmax read per-thread
#pragma unroll
    for (int g = 0; g < 4; g++) {
      int r = g * 16 + gid;
      float4 x0 = *(const float4*)&rmx[r * 16];
      float4 x1 = *(const float4*)&rmx[r * 16 + 4];
      float4 x2 = *(const float4*)&rmx[r * 16 + 8];
      float4 x3 = *(const float4*)&rmx[r * 16 + 12];
      float r0 = fmaxf(fmaxf(fmaxf(x0.x, x0.y), fmaxf(x0.z, x0.w)),
                       fmaxf(fmaxf(x1.x, x1.y), fmaxf(x1.z, x1.w)));
      r0 = fmaxf(r0, fmaxf(fmaxf(fmaxf(x2.x, x2.y), fmaxf(x2.z, x2.w)),
                           fmaxf(fmaxf(x3.x, x3.y), fmaxf(x3.z, x3.w))));
      float4 y0 = *(const float4*)&rmx[(r + 8) * 16];
      float4 y1 = *(const float4*)&rmx[(r + 8) * 16 + 4];
      float4 y2 = *(const float4*)&rmx[(r + 8) * 16 + 8];
      float4 y3 = *(const float4*)&rmx[(r + 8) * 16 + 12];
      float r1 = fmaxf(fmaxf(fmaxf(y0.x, y0.y), fmaxf(y0.z, y0.w)),
                       fmaxf(fmaxf(y1.x, y1.y), fmaxf(y1.z, y1.w)));
      r1 = fmaxf(r1, fmaxf(fmaxf(fmaxf(y2.x, y2.y), fmaxf(y2.z, y2.w)),
                           fmaxf(fmaxf(y3.x, y3.y), fmaxf(y3.z, y3.w))));
      float sub0 = diag_s[r] + r0, sub1 = diag_s[r + 8] + r1;
      float ds0 = 0.f, ds1 = 0.f;
#pragma unroll
      for (int mt = 0; mt < 2; mt++) {
        int m = m0 + mt * 8 + 2 * tig;
        float q0 = RATIO * (__expf(dfrag[g][mt][0] - sub0) + EPSV);
        float q1 = RATIO * (__expf(dfrag[g][mt][1] - sub0) + EPSV);
        float q2 = RATIO * (__expf(dfrag[g][mt][2] - sub1) + EPSV);
        float q3 = RATIO * (__expf(dfrag[g][mt][3] - sub1) + EPSV);
        ds0 += q0 * ksv[mt][0] + q1 * ksv[mt][1];
        ds1 += q2 * ksv[mt][0] + q3 * ksv[mt][1];
        *(float2*)&bufP[r * QP_S + m] = make_float2(rnaf(q0), rnaf(q1));
        *(float2*)&bufP[(r + 8) * QP_S + m] = make_float2(rnaf(q2), rnaf(q3));
      }
      ds0 += __shfl_xor_sync(0xffffffffu, ds0, 1);
      ds0 += __shfl_xor_sync(0xffffffffu, ds0, 2);
      ds1 += __shfl_xor_sync(0xffffffffu, ds1, 1);
      ds1 += __shfl_xor_sync(0xffffffffu, ds1, 2);
      if (tig == 0) {
        den[r * 16 + wid] = ds0;
        den[(r + 8) * 16 + wid] = ds1;
      }
    }
    __syncthreads();  // qp + den ready

    // out = q' @ ctx
    float ofrag[2][4];
#pragma unroll
    for (int et = 0; et < 2; et++)
#pragma unroll
      for (int j = 0; j < 4; j++) ofrag[et][j] = 0.f;

#pragma unroll 8
    for (int ks = 0; ks < 32; ks++) {
      unsigned a[4], b[4];
      ldsm4(a, u_P + (unsigned)(rg * QP_S + ks * 8 + aoQP) * 4u);
      ldsm4(b, u_C + (unsigned)(eh * CT_S + ks * 8 + boCT) * 4u);
      mma8(ofrag[0], a, b);
      mma8(ofrag[1], a, b + 2);
    }

    // denom read per-thread (broadcast LDS.128)
    float inv0, inv1;
    {
      int r = rg + gid;
      float4 a0 = *(const float4*)&den[r * 16];
      float4 a1 = *(const float4*)&den[r * 16 + 4];
      float4 a2 = *(const float4*)&den[r * 16 + 8];
      float4 a3 = *(const float4*)&den[r * 16 + 12];
      float s0 = (a0.x + a0.y + a0.z + a0.w) + (a1.x + a1.y + a1.z + a1.w) +
                 (a2.x + a2.y + a2.z + a2.w) + (a3.x + a3.y + a3.z + a3.w);
      float4 b0 = *(const float4*)&den[(r + 8) * 16];
      float4 b1 = *(const float4*)&den[(r + 8) * 16 + 4];
      float4 b2 = *(const float4*)&den[(r + 8) * 16 + 8];
      float4 b3 = *(const float4*)&den[(r + 8) * 16 + 12];
      float s1 = (b0.x + b0.y + b0.z + b0.w) + (b1.x + b1.y + b1.z + b1.w) +
                 (b2.x + b2.y + b2.z + b2.w) + (b3.x + b3.y + b3.z + b3.w);
      inv0 = 1.f / s0;
      inv1 = 1.f / s1;
    }

    float* ob = outg + ((size_t)bh * Nn + (size_t)t * 64) * Dn;
#pragma unroll
    for (int et = 0; et < 2; et++) {
      int e = eh + et * 8 + 2 * tig;
      int r = rg + gid;
      *(float2*)&ob[r * Dn + e] =
          make_float2(ofrag[et][0] * inv0, ofrag[et][1] * inv0);
      *(float2*)&ob[(r + 8) * Dn + e] =
          make_float2(ofrag[et][2] * inv1, ofrag[et][3] * inv1);
    }
  }
}

// ---------------------------------------------------------------------------
extern "C" void kernel_launch(void* const* d_in, const int* in_sizes, int n_in,
                              void* d_out, int out_size) {
  const float* q    = (const float*)d_in[0];
  const float* k    = (const float*)d_in[1];
  const float* v    = (const float*)d_in[2];
  const float* proj = (const float*)d_in[3];
  float* out = (float*)d_out;

  const int smem =
      (17408 + 17152 + 4352 * 2 + 4352 * 2 + 64 + 64 + 32 + 256 + 1024 +
       1024) * 4;

  cudaFuncSetAttribute(fused_kernel, cudaFuncAttributeMaxDynamicSharedMemorySize, smem);
  fused_kernel<<<BHn, 512, smem>>>(q, k, v, proj, out);
}

// round 11
// speedup vs baseline: 2.3325x; 1.3633x over previous
#include <cuda_runtime.h>
#include <cuda_bf16.h>

// Performer FAVOR+ — fused persistent kernel, bf16 m16n8k16 mma + ldmatrix.
// dash: 3-pass compensated bf16 (hi/lo Dekker planes) -> ~fp32 accuracy.
// E^T@V and q'@ctx: single-plane RN bf16 (errors average out in positive sums).

#define BHn 128
#define Nn  4096
#define Dn  64
#define Mn  256
#define NTILES 64

#define NORMV 0.35355339059327378f
#define RATIO 0.0625f
#define EPSV  1e-4f

// bf16-element strides (mult of 8 for 16B rows; S/2 ≡ 4 mod 8 -> conflict-free)
#define KQS 72
#define VTS 72
#define ETS 72
#define PJS 72
#define QPS 264
#define CTS 264

__device__ __forceinline__ void mma16(float d[4], const unsigned a[4],
                                      const unsigned b[2]) {
  asm volatile(
      "mma.sync.aligned.m16n8k16.row.col.f32.bf16.bf16.f32 "
      "{%0,%1,%2,%3},{%4,%5,%6,%7},{%8,%9},{%0,%1,%2,%3};"
      : "+f"(d[0]), "+f"(d[1]), "+f"(d[2]), "+f"(d[3])
      : "r"(a[0]), "r"(a[1]), "r"(a[2]), "r"(a[3]), "r"(b[0]), "r"(b[1]));
}
__device__ __forceinline__ void ldsm4(unsigned r[4], unsigned addr) {
  asm volatile(
      "ldmatrix.sync.aligned.m8n8.x4.shared.b16 {%0,%1,%2,%3}, [%4];"
      : "=r"(r[0]), "=r"(r[1]), "=r"(r[2]), "=r"(r[3]) : "r"(addr));
}
__device__ __forceinline__ unsigned s2u(const void* p) {
  return (unsigned)__cvta_generic_to_shared(p);
}
// pack two floats -> bf16x2 (a -> lower, b -> upper)
__device__ __forceinline__ unsigned pk2(float a, float b) {
  unsigned r;
  asm("cvt.rn.bf16x2.f32 %0, %1, %2;" : "=r"(r) : "f"(b), "f"(a));
  return r;
}
__device__ __forceinline__ float lof(unsigned u) {
  return __uint_as_float(u << 16);
}
__device__ __forceinline__ float hif(unsigned u) {
  return __uint_as_float(u & 0xffff0000u);
}
__device__ __forceinline__ __nv_bfloat16 b16(float x) {
  return __float2bfloat16_rn(x);
}
// A-style m16k16 fragment offset (bf16 elems): tiles r0-7/r8-15 × k0-7/k8-15
__device__ __forceinline__ int a16o(int lane, int S) {
  return ((lane & 7) + ((lane >> 3) & 1) * 8) * S + (lane >> 4) * 8;
}
// B-style n16k16 (B[n][k] n-major): tiles n0-7/n8-15 × k0-7/k8-15
__device__ __forceinline__ int b16o(int lane, int S) {
  return ((lane & 7) + (lane >> 4) * 8) * S + ((lane >> 3) & 1) * 8;
}

// ---------------------------------------------------------------------------
__global__ __launch_bounds__(512, 1) void fused_kernel(
    const float* __restrict__ qg, const float* __restrict__ kg,
    const float* __restrict__ vg, const float* __restrict__ projg,
    float* __restrict__ outg) {
  extern __shared__ float sm[];
  float* bufP   = sm;                 // 18432 f: proj hi+lo -> E_T -> qp (bf16)
  float* bufC   = bufP + 18432;       // 8448 f: ctx bf16 [64][264]
  float* vT0f   = bufC + 8448;        // 2304 f
  float* vT1f   = vT0f + 2304;        // 2304 f
  float* kqhf   = vT1f + 2304;        // 2304 f
  float* kqlf   = kqhf + 2304;        // 2304 f
  float* diag_s = kqlf + 2304;        // 64
  float* vsum_s = diag_s + 64;        // 64
  float* red_s  = vsum_s + 64;        // 32
  float* ksum_s = red_s + 32;         // 256
  float* rmx    = ksum_s + 256;       // 1024 [64][16] (+vsum scratch)
  float* den    = rmx + 1024;         // 1024 [64][16]

  __nv_bfloat16* bufPb = (__nv_bfloat16*)bufP;
  __nv_bfloat16* bufCb = (__nv_bfloat16*)bufC;
  __nv_bfloat16* kqhb  = (__nv_bfloat16*)kqhf;
  __nv_bfloat16* kqlb  = (__nv_bfloat16*)kqlf;

  const int bh = blockIdx.x, tid = threadIdx.x;
  const int lane = tid & 31, wid = tid >> 5;
  const int gid = lane >> 2, tig = lane & 3;
  const int m0 = wid * 16;

  const unsigned u_P = s2u(bufP), u_C = s2u(bufC);
  const unsigned u_vT0 = s2u(vT0f), u_vT1 = s2u(vT1f);
  const unsigned u_kh = s2u(kqhf), u_kl = s2u(kqlf);
  const int aKQ = a16o(lane, KQS), bVT = b16o(lane, VTS);
  const int aET = a16o(lane, ETS), bPJ = b16o(lane, PJS);
  const int aQP = a16o(lane, QPS), bCT = b16o(lane, CTS);

  const float4* kb4 = (const float4*)(kg + (size_t)bh * Nn * Dn);
  const float4* vb4 = (const float4*)(vg + (size_t)bh * Nn * Dn);
  const float4* qb4 = (const float4*)(qg + (size_t)bh * Nn * Dn);

  // ---- proj -> two bf16 planes in smem; extract B fragments to registers ----
  {
    __nv_bfloat16* phi = bufPb;               // [256][72]
    __nv_bfloat16* plo = bufPb + 256 * PJS;   // [256][72]
    for (int i = tid; i < 4096; i += 512) {
      float4 p = ((const float4*)projg)[i];
      int r = i >> 4, c4 = (i & 15) * 4;
      unsigned h01 = pk2(p.x, p.y), h23 = pk2(p.z, p.w);
      *(uint2*)&phi[r * PJS + c4] = make_uint2(h01, h23);
      unsigned l01 = pk2(p.x - lof(h01), p.y - hif(h01));
      unsigned l23 = pk2(p.z - lof(h23), p.w - hif(h23));
      *(uint2*)&plo[r * PJS + c4] = make_uint2(l01, l23);
    }
  }
  __syncthreads();
  unsigned pBh[4][4], pBl[4][4];
#pragma unroll
  for (int ks = 0; ks < 4; ks++) {
    ldsm4(pBh[ks], u_P + (unsigned)(m0 * PJS + ks * 16 + bPJ) * 2u);
    ldsm4(pBl[ks], u_P + (unsigned)((256 + m0) * PJS + ks * 16 + bPJ) * 2u);
  }
  __syncthreads();  // bufP free

  // =======================================================================
  // K/V pass (2 syncs per tile)
  // =======================================================================
  float C2[8][4];
#pragma unroll
  for (int e = 0; e < 8; e++)
#pragma unroll
    for (int j = 0; j < 4; j++) C2[e][j] = 0.f;
  float uacc[2][2] = {};
  float4 vsum4 = make_float4(0.f, 0.f, 0.f, 0.f);
  float dmax = -1e30f;

  float4 kpre[2], vpre[2];
  kpre[0] = kb4[tid]; kpre[1] = kb4[512 + tid];
  vpre[0] = vb4[tid]; vpre[1] = vb4[512 + tid];

  for (int t = 0; t < NTILES; t++) {
    __nv_bfloat16* vTb = (__nv_bfloat16*)((t & 1) ? vT1f : vT0f);
    const unsigned u_vT = (t & 1) ? u_vT1 : u_vT0;
#pragma unroll
    for (int u = 0; u < 2; u++) {
      int i = u * 512 + tid;
      int r = i >> 4, c4 = (i & 15) * 4;
      float4 kv = kpre[u];
      kv.x *= NORMV; kv.y *= NORMV; kv.z *= NORMV; kv.w *= NORMV;
      unsigned h01 = pk2(kv.x, kv.y), h23 = pk2(kv.z, kv.w);
      *(uint2*)&kqhb[r * KQS + c4] = make_uint2(h01, h23);
      unsigned l01 = pk2(kv.x - lof(h01), kv.y - hif(h01));
      unsigned l23 = pk2(kv.z - lof(h23), kv.w - hif(h23));
      *(uint2*)&kqlb[r * KQS + c4] = make_uint2(l01, l23);
      float s = kv.x * kv.x + kv.y * kv.y + kv.z * kv.z + kv.w * kv.w;
      s += __shfl_xor_sync(0xffffffffu, s, 1);
      s += __shfl_xor_sync(0xffffffffu, s, 2);
      s += __shfl_xor_sync(0xffffffffu, s, 4);
      s += __shfl_xor_sync(0xffffffffu, s, 8);
      if ((tid & 15) == 0) diag_s[r] = 0.5f * s;
      float4 vv = vpre[u];
      vsum4.x += vv.x; vsum4.y += vv.y; vsum4.z += vv.z; vsum4.w += vv.w;
      vTb[(c4 + 0) * VTS + r] = b16(vv.x);
      vTb[(c4 + 1) * VTS + r] = b16(vv.y);
      vTb[(c4 + 2) * VTS + r] = b16(vv.z);
      vTb[(c4 + 3) * VTS + r] = b16(vv.w);
    }
    if (t < NTILES - 1) {
      kpre[0] = kb4[(t + 1) * 1024 + tid];
      kpre[1] = kb4[(t + 1) * 1024 + 512 + tid];
      vpre[0] = vb4[(t + 1) * 1024 + tid];
      vpre[1] = vb4[(t + 1) * 1024 + 512 + tid];
    }
    __syncthreads();  // staged + diag ready; prev C-mma done (bufP writable)

    // dash = k @ proj^T: 3-pass compensated bf16
    float dfrag[4][2][4];
#pragma unroll
    for (int g = 0; g < 4; g++)
#pragma unroll
      for (int mt = 0; mt < 2; mt++)
#pragma unroll
        for (int j = 0; j < 4; j++) dfrag[g][mt][j] = 0.f;

#pragma unroll
    for (int ks = 0; ks < 4; ks++) {
#pragma unroll
      for (int g = 0; g < 4; g++) {
        unsigned ah[4], al[4];
        ldsm4(ah, u_kh + (unsigned)(g * 16 * KQS + ks * 16 + aKQ) * 2u);
        ldsm4(al, u_kl + (unsigned)(g * 16 * KQS + ks * 16 + aKQ) * 2u);
        mma16(dfrag[g][0], ah, pBh[ks]);
        mma16(dfrag[g][0], al, pBh[ks]);
        mma16(dfrag[g][0], ah, pBl[ks]);
        mma16(dfrag[g][1], ah, pBh[ks] + 2);
        mma16(dfrag[g][1], al, pBh[ks] + 2);
        mma16(dfrag[g][1], ah, pBl[ks] + 2);
      }
    }

    // exp -> E_T (bufP bf16 [256][72]); U and max
#pragma unroll
    for (int g = 0; g < 4; g++) {
      int r = g * 16 + gid;
      float dg0 = diag_s[r], dg1 = diag_s[r + 8];
#pragma unroll
      for (int mt = 0; mt < 2; mt++) {
        int m = m0 + mt * 8 + 2 * tig;
        float d0 = dfrag[g][mt][0], d1 = dfrag[g][mt][1];
        float d2 = dfrag[g][mt][2], d3 = dfrag[g][mt][3];
        dmax = fmaxf(dmax, fmaxf(fmaxf(d0, d1), fmaxf(d2, d3)));
        float e0 = __expf(d0 - dg0), e1 = __expf(d1 - dg0);
        float e2 = __expf(d2 - dg1), e3 = __expf(d3 - dg1);
        uacc[mt][0] += e0 + e2;
        uacc[mt][1] += e1 + e3;
        bufPb[m * ETS + r]           = b16(e0);
        bufPb[(m + 1) * ETS + r]     = b16(e1);
        bufPb[m * ETS + r + 8]       = b16(e2);
        bufPb[(m + 1) * ETS + r + 8] = b16(e3);
      }
    }
    __syncthreads();  // E ready

    // C2 += E^T(m-slice) @ V
#pragma unroll
    for (int ks = 0; ks < 4; ks++) {
      unsigned a[4];
      ldsm4(a, u_P + (unsigned)(m0 * ETS + ks * 16 + aET) * 2u);
#pragma unroll
      for (int ep = 0; ep < 4; ep++) {
        unsigned b[4];
        ldsm4(b, u_vT + (unsigned)(ep * 16 * VTS + ks * 16 + bVT) * 2u);
        mma16(C2[ep * 2], a, b);
        mma16(C2[ep * 2 + 1], a, b + 2);
      }
    }
  }

  // ---- finalize ksum + ctx (all in smem) ----
  float wm = dmax;
#pragma unroll
  for (int off = 16; off; off >>= 1)
    wm = fmaxf(wm, __shfl_xor_sync(0xffffffffu, wm, off));
  if (lane == 0) red_s[wid] = wm;
  vsum4.x += __shfl_xor_sync(0xffffffffu, vsum4.x, 16);
  vsum4.y += __shfl_xor_sync(0xffffffffu, vsum4.y, 16);
  vsum4.z += __shfl_xor_sync(0xffffffffu, vsum4.z, 16);
  vsum4.w += __shfl_xor_sync(0xffffffffu, vsum4.w, 16);
  if (lane < 16) *(float4*)&rmx[wid * 64 + lane * 4] = vsum4;
  __syncthreads();
  if (tid == 0) {
    float mm = red_s[0];
#pragma unroll
    for (int w = 1; w < 16; w++) mm = fmaxf(mm, red_s[w]);
    red_s[16] = mm;
  }
  if (tid < 64) {
    float s = 0.f;
#pragma unroll
    for (int w = 0; w < 16; w++) s += rmx[w * 64 + tid];
    vsum_s[tid] = s;
  }
  __syncthreads();
  const float scale = __expf(-red_s[16]);

#pragma unroll
  for (int mt = 0; mt < 2; mt++) {
#pragma unroll
    for (int j = 0; j < 2; j++) {
      float u = uacc[mt][j];
      u += __shfl_xor_sync(0xffffffffu, u, 4);
      u += __shfl_xor_sync(0xffffffffu, u, 8);
      u += __shfl_xor_sync(0xffffffffu, u, 16);
      if (gid == 0)
        ksum_s[m0 + mt * 8 + 2 * tig + j] =
            RATIO * (scale * u + EPSV * (float)Nn);
    }
  }

  {
    int m = m0 + gid;
#pragma unroll
    for (int et = 0; et < 8; et++) {
      int e = et * 8 + 2 * tig;
      bufCb[e * CTS + m]           = b16(RATIO * (scale * C2[et][0] + EPSV * vsum_s[e]));
      bufCb[(e + 1) * CTS + m]     = b16(RATIO * (scale * C2[et][1] + EPSV * vsum_s[e + 1]));
      bufCb[e * CTS + m + 8]       = b16(RATIO * (scale * C2[et][2] + EPSV * vsum_s[e]));
      bufCb[(e + 1) * CTS + m + 8] = b16(RATIO * (scale * C2[et][3] + EPSV * vsum_s[e + 1]));
    }
  }
  __syncthreads();  // ctx + ksum ready

  // =======================================================================
  // Q pass: 64 tiles, 3 syncs per tile
  // =======================================================================
  float ksv[2][2];
#pragma unroll
  for (int mt = 0; mt < 2; mt++) {
    ksv[mt][0] = ksum_s[m0 + mt * 8 + 2 * tig];
    ksv[mt][1] = ksum_s[m0 + mt * 8 + 2 * tig + 1];
  }
  const int rg = (wid & 3) * 16;
  const int eh = (wid >> 2) * 16;

  float4 qpre[2];
  qpre[0] = qb4[tid]; qpre[1] = qb4[512 + tid];

  for (int t = 0; t < NTILES; t++) {
#pragma unroll
    for (int u = 0; u < 2; u++) {
      int i = u * 512 + tid;
      int r = i >> 4, c4 = (i & 15) * 4;
      float4 qv = qpre[u];
      qv.x *= NORMV; qv.y *= NORMV; qv.z *= NORMV; qv.w *= NORMV;
      unsigned h01 = pk2(qv.x, qv.y), h23 = pk2(qv.z, qv.w);
      *(uint2*)&kqhb[r * KQS + c4] = make_uint2(h01, h23);
      unsigned l01 = pk2(qv.x - lof(h01), qv.y - hif(h01));
      unsigned l23 = pk2(qv.z - lof(h23), qv.w - hif(h23));
      *(uint2*)&kqlb[r * KQS + c4] = make_uint2(l01, l23);
      float s = qv.x * qv.x + qv.y * qv.y + qv.z * qv.z + qv.w * qv.w;
      s += __shfl_xor_sync(0xffffffffu, s, 1);
      s += __shfl_xor_sync(0xffffffffu, s, 2);
      s += __shfl_xor_sync(0xffffffffu, s, 4);
      s += __shfl_xor_sync(0xffffffffu, s, 8);
      if ((tid & 15) == 0) diag_s[r] = 0.5f * s;
    }
    if (t < NTILES - 1) {
      qpre[0] = qb4[(t + 1) * 1024 + tid];
      qpre[1] = qb4[(t + 1) * 1024 + 512 + tid];
    }
    __syncthreads();  // staged + diag ready; prev out-mma done

    float dfrag[4][2][4];
#pragma unroll
    for (int g = 0; g < 4; g++)
#pragma unroll
      for (int mt = 0; mt < 2; mt++)
#pragma unroll
        for (int j = 0; j < 4; j++) dfrag[g][mt][j] = 0.f;

#pragma unroll
    for (int ks = 0; ks < 4; ks++) {
#pragma unroll
      for (int g = 0; g < 4; g++) {
        unsigned ah[4], al[4];
        ldsm4(ah, u_kh + (unsigned)(g * 16 * KQS + ks * 16 + aKQ) * 2u);
        ldsm4(al, u_kl + (unsigned)(g * 16 * KQS + ks * 16 + aKQ) * 2u);
        mma16(dfrag[g][0], ah, pBh[ks]);
        mma16(dfrag[g][0], al, pBh[ks]);
        mma16(dfrag[g][0], ah, pBl[ks]);
        mma16(dfrag[g][1], ah, pBh[ks] + 2);
        mma16(dfrag[g][1], al, pBh[ks] + 2);
        mma16(dfrag[g][1], ah, pBl[ks] + 2);
      }
    }

    // per-warp row-max partials
#pragma unroll
    for (int g = 0; g < 4; g++) {
      float mlo = -1e30f, mhi = -1e30f;
#pragma unroll
      for (int mt = 0; mt < 2; mt++) {
        mlo = fmaxf(mlo, fmaxf(dfrag[g][mt][0], dfrag[g][mt][1]));
        mhi = fmaxf(mhi, fmaxf(dfrag[g][mt][2], dfrag[g][mt][3]));
      }
      mlo = fmaxf(mlo, __shfl_xor_sync(0xffffffffu, mlo, 1));
      mlo = fmaxf(mlo, __shfl_xor_sync(0xffffffffu, mlo, 2));
      mhi = fmaxf(mhi, __shfl_xor_sync(0xffffffffu, mhi, 1));
      mhi = fmaxf(mhi, __shfl_xor_sync(0xffffffffu, mhi, 2));
      if (tig == 0) {
        rmx[(g * 16 + gid) * 16 + wid] = mlo;
        rmx[(g * 16 + gid + 8) * 16 + wid] = mhi;
      }
    }
    __syncthreads();  // rmx ready

    // q' = ratio*(exp(dash - diag - rowmax) + eps) -> bufP bf16 [64][264]
#pragma unroll
    for (int g = 0; g < 4; g++) {
      int r = g * 16 + gid;
      float4 x0 = *(const float4*)&rmx[r * 16];
      float4 x1 = *(const float4*)&rmx[r * 16 + 4];
      float4 x2 = *(const float4*)&rmx[r * 16 + 8];
      float4 x3 = *(const float4*)&rmx[r * 16 + 12];
      float r0 = fmaxf(fmaxf(fmaxf(x0.x, x0.y), fmaxf(x0.z, x0.w)),
                       fmaxf(fmaxf(x1.x, x1.y), fmaxf(x1.z, x1.w)));
      r0 = fmaxf(r0, fmaxf(fmaxf(fmaxf(x2.x, x2.y), fmaxf(x2.z, x2.w)),
                           fmaxf(fmaxf(x3.x, x3.y), fmaxf(x3.z, x3.w))));
      float4 y0 = *(const float4*)&rmx[(r + 8) * 16];
      float4 y1 = *(const float4*)&rmx[(r + 8) * 16 + 4];
      float4 y2 = *(const float4*)&rmx[(r + 8) * 16 + 8];
      float4 y3 = *(const float4*)&rmx[(r + 8) * 16 + 12];
      float r1 = fmaxf(fmaxf(fmaxf(y0.x, y0.y), fmaxf(y0.z, y0.w)),
                       fmaxf(fmaxf(y1.x, y1.y), fmaxf(y1.z, y1.w)));
      r1 = fmaxf(r1, fmaxf(fmaxf(fmaxf(y2.x, y2.y), fmaxf(y2.z, y2.w)),
                           fmaxf(fmaxf(y3.x, y3.y), fmaxf(y3.z, y3.w))));
      float sub0 = diag_s[r] + r0, sub1 = diag_s[r + 8] + r1;
      float ds0 = 0.f, ds1 = 0.f;
#pragma unroll
      for (int mt = 0; mt < 2; mt++) {
        int m = m0 + mt * 8 + 2 * tig;
        float q0 = RATIO * (__expf(dfrag[g][mt][0] - sub0) + EPSV);
        float q1 = RATIO * (__expf(dfrag[g][mt][1] - sub0) + EPSV);
        float q2 = RATIO * (__expf(dfrag[g][mt][2] - sub1) + EPSV);
        float q3 = RATIO * (__expf(dfrag[g][mt][3] - sub1) + EPSV);
        ds0 += q0 * ksv[mt][0] + q1 * ksv[mt][1];
        ds1 += q2 * ksv[mt][0] + q3 * ksv[mt][1];
        *(unsigned*)&bufPb[r * QPS + m] = pk2(q0, q1);
        *(unsigned*)&bufPb[(r + 8) * QPS + m] = pk2(q2, q3);
      }
      ds0 += __shfl_xor_sync(0xffffffffu, ds0, 1);
      ds0 += __shfl_xor_sync(0xffffffffu, ds0, 2);
      ds1 += __shfl_xor_sync(0xffffffffu, ds1, 1);
      ds1 += __shfl_xor_sync(0xffffffffu, ds1, 2);
      if (tig == 0) {
        den[r * 16 + wid] = ds0;
        den[(r + 8) * 16 + wid] = ds1;
      }
    }
    __syncthreads();  // qp + den ready

    // out = q' @ ctx  (K = m = 256 -> 16 k16 steps)
    float ofrag[2][4];
#pragma unroll
    for (int et = 0; et < 2; et++)
#pragma unroll
      for (int j = 0; j < 4; j++) ofrag[et][j] = 0.f;

#pragma unroll 4
    for (int ks = 0; ks < 16; ks++) {
      unsigned a[4], b[4];
      ldsm4(a, u_P + (unsigned)(rg * QPS + ks * 16 + aQP) * 2u);
      ldsm4(b, u_C + (unsigned)(eh * CTS + ks * 16 + bCT) * 2u);
      mma16(ofrag[0], a, b);
      mma16(ofrag[1], a, b + 2);
    }

    float inv0, inv1;
    {
      int r = rg + gid;
      float4 a0 = *(const float4*)&den[r * 16];
      float4 a1 = *(const float4*)&den[r * 16 + 4];
      float4 a2 = *(const float4*)&den[r * 16 + 8];
      float4 a3 = *(const float4*)&den[r * 16 + 12];
      float s0 = (a0.x + a0.y + a0.z + a0.w) + (a1.x + a1.y + a1.z + a1.w) +
                 (a2.x + a2.y + a2.z + a2.w) + (a3.x + a3.y + a3.z + a3.w);
      float4 b0 = *(const float4*)&den[(r + 8) * 16];
      float4 b1 = *(const float4*)&den[(r + 8) * 16 + 4];
      float4 b2 = *(const float4*)&den[(r + 8) * 16 + 8];
      float4 b3 = *(const float4*)&den[(r + 8) * 16 + 12];
      float s1 = (b0.x + b0.y + b0.z + b0.w) + (b1.x + b1.y + b1.z + b1.w) +
                 (b2.x + b2.y + b2.z + b2.w) + (b3.x + b3.y + b3.z + b3.w);
      inv0 = 1.f / s0;
      inv1 = 1.f / s1;
    }

    float* ob = outg + ((size_t)bh * Nn + (size_t)t * 64) * Dn;
#pragma unroll
    for (int et = 0; et < 2; et++) {
      int e = eh + et * 8 + 2 * tig;
      int r = rg + gid;
      *(float2*)&ob[r * Dn + e] =
          make_float2(ofrag[et][0] * inv0, ofrag[et][1] * inv0);
      *(float2*)&ob[(r + 8) * Dn + e] =
          make_float2(ofrag[et][2] * inv1, ofrag[et][3] * inv1);
    }
  }
}

// ---------------------------------------------------------------------------
extern "C" void kernel_launch(void* const* d_in, const int* in_sizes, int n_in,
                              void* d_out, int out_size) {
  const float* q    = (const float*)d_in[0];
  const float* k    = (const float*)d_in[1];
  const float* v    = (const float*)d_in[2];
  const float* proj = (const float*)d_in[3];
  float* out = (float*)d_out;

  const int smem =
      (18432 + 8448 + 2304 * 2 + 2304 * 2 + 64 + 64 + 32 + 256 + 1024 + 1024) *
      4;

  cudaFuncSetAttribute(fused_kernel, cudaFuncAttributeMaxDynamicSharedMemorySize, smem);
  fused_kernel<<<BHn, 512, smem>>>(q, k, v, proj, out);
}